// round 1
// baseline (speedup 1.0000x reference)
#include <cuda_runtime.h>
#include <cuda_fp16.h>

#define Bq 32
#define Tq 1024
#define Iq 64
#define Hq 512
#define Aq 16

#define OUT_N  (Bq*Tq*Aq)          // 524288
#define HN_N   (Bq*Hq)             // 16384
#define HN_OFF OUT_N
#define RNN_OFF (OUT_N + HN_N)     // 540672

#define GRNN 128                   // persistent RNN blocks (must be <= resident CTAs)
#define JPB  4                     // Hq / GRNN columns per block
#define HP   520                   // padded fp16 h row (bank-conflict-free, 16B-aligned rows)
#define WP   516                   // padded fp32 W row

// ---- scratch (static device globals: allocation-free) ----
__device__ float  g_xp[Tq*Bq*Hq];       // x_proj [t][b][j]   (64 MB)
__device__ float  g_hidden[Bq*Tq*Hq];   // fc1 output [row][k] (64 MB)
__device__ __align__(16) __half g_h16[2][Bq*Hq]; // h state transport, double-buffered
__device__ unsigned g_count;
__device__ unsigned g_gen;

// ---------------- grid-wide barrier (generation counter, replay-safe) ----------------
__device__ __forceinline__ void grid_barrier(int nb) {
    __syncthreads();
    if (threadIdx.x == 0) {
        __threadfence();
        volatile unsigned* genp = &g_gen;
        unsigned my = *genp;
        unsigned old = atomicAdd(&g_count, 1u);
        if (old == (unsigned)(nb - 1)) {
            atomicExch(&g_count, 0u);
            __threadfence();
            atomicAdd(&g_gen, 1u);
        } else {
            while (*genp == my) { }
        }
        __threadfence();
    }
    __syncthreads();
}

// ---------------- x_proj: xp[t][b][j] = sum_i inp[b][t][i] * w_ih[i][j] ----------------
__global__ void xp_kernel(const float* __restrict__ inp, const float* __restrict__ w_ih) {
    const int b   = blockIdx.x;   // 32
    const int tc  = blockIdx.y;   // 32 chunks of 32 timesteps
    const int tid = threadIdx.x;  // 512 (j)
    __shared__ float s_in[32*64];
    const float* src = inp + (size_t)b*Tq*Iq + (size_t)tc*32*Iq; // contiguous 2048 floats
    ((float4*)s_in)[tid] = ((const float4*)src)[tid];
    __syncthreads();

    float acc[32];
    #pragma unroll
    for (int tt = 0; tt < 32; tt++) acc[tt] = 0.f;

    #pragma unroll 8
    for (int i = 0; i < Iq; i++) {
        float w = w_ih[i*Hq + tid];
        #pragma unroll
        for (int tt = 0; tt < 32; tt++)
            acc[tt] = fmaf(s_in[tt*64 + i], w, acc[tt]);
    }
    #pragma unroll
    for (int tt = 0; tt < 32; tt++)
        g_xp[(size_t)(tc*32 + tt)*(Bq*Hq) + b*Hq + tid] = acc[tt];
}

// ---------------- persistent RNN scan ----------------
// block owns 4 output columns of w_hh (weight-stationary in SMEM).
// thread (ks, b, jl): partial dot over half the k range; reduce pairs via SMEM.
__global__ void __launch_bounds__(256, 1)
rnn_kernel(const float* __restrict__ hn, const float* __restrict__ w_hh,
           float* __restrict__ outbuf) {
    __shared__ __align__(16) __half h_s[32*HP];
    __shared__ float W_s[JPB*WP];
    __shared__ float psum[256];

    const int tid = threadIdx.x;
    const int bid = blockIdx.x;
    const int j0  = bid * JPB;

    // stationary weight slice: W_s[jl][k] = w_hh[k][j0+jl]
    for (int e = tid; e < JPB*Hq; e += 256) {
        int jl = e >> 9;
        int k  = e & 511;
        W_s[jl*WP + k] = w_hh[k*Hq + j0 + jl];
    }
    // h_0 = hn -> fp16 transport buffer 0
    for (int e = bid*256 + tid; e < Bq*Hq; e += GRNN*256)
        g_h16[0][e] = __float2half(hn[e]);

    grid_barrier(GRNN);

    const int jl    = tid & 3;
    const int bb    = (tid >> 2) & 31;
    const int ks    = tid >> 7;       // 0/1: k-split
    const int kbase = ks << 8;        // 0 or 256

    for (int t = 0; t < Tq; t++) {
        // stage full h state (fp16, 32 KB) into padded SMEM, L1-bypassing loads
        const int4* src = (const int4*)g_h16[t & 1];
        for (int e = tid; e < 2048; e += 256) {
            int row = e >> 6;
            int col = e & 63;
            ((int4*)(&h_s[row*HP]))[col] = __ldcg(&src[row*64 + col]);
        }
        __syncthreads();

        const __half* hrow = &h_s[bb*HP + kbase];
        const float*  wrow = &W_s[jl*WP + kbase];
        float acc = 0.f;
        #pragma unroll
        for (int k = 0; k < 256; k += 4) {
            float4  wv  = *(const float4*)(wrow + k);
            __half2 h01 = *(const __half2*)(hrow + k);
            __half2 h23 = *(const __half2*)(hrow + k + 2);
            float2  f01 = __half22float2(h01);
            float2  f23 = __half22float2(h23);
            acc = fmaf(f01.x, wv.x, acc);
            acc = fmaf(f01.y, wv.y, acc);
            acc = fmaf(f23.x, wv.z, acc);
            acc = fmaf(f23.y, wv.w, acc);
        }
        psum[tid] = acc;
        __syncthreads();

        if (tid < 128) {
            int b2 = tid >> 2;
            int j2 = (tid & 3) + j0;
            float v = psum[tid] + psum[tid + 128]
                    + g_xp[(size_t)t*(Bq*Hq) + b2*Hq + j2];
            float hval = 1.f / (1.f + __expf(-v));
            outbuf[RNN_OFF + (size_t)b2*Tq*Hq + (size_t)t*Hq + j2] = hval;  // rnn_out (fp32 exact)
            g_h16[(t + 1) & 1][b2*Hq + j2] = __float2half(hval);           // transport
            if (t == Tq - 1)
                outbuf[HN_OFF + b2*Hq + j2] = hval;                        // hn_last
        }
        grid_barrier(GRNN);
    }
}

// ---------------- fc1: hidden = relu(rnn_out @ fc1_w + b1), 64x64 tiles ----------------
__global__ void fc1_kernel(const float* __restrict__ A,   // [32768, 512] = rnn_out
                           const float* __restrict__ W,   // [512, 512]
                           const float* __restrict__ bias) {
    __shared__ float As[64*16];
    __shared__ float Ws[16*64];
    const int tid = threadIdx.x;      // 256
    const int bx = blockIdx.x;        // 8 col tiles
    const int by = blockIdx.y;        // 512 row tiles
    const int tx = tid & 15, ty = tid >> 4;
    const int row0 = by*64, col0 = bx*64;

    float acc[4][4];
    #pragma unroll
    for (int i = 0; i < 4; i++)
        #pragma unroll
        for (int j = 0; j < 4; j++) acc[i][j] = 0.f;

    for (int kt = 0; kt < Hq; kt += 16) {
        {
            int r  = tid >> 2, kq = (tid & 3) << 2;
            *(float4*)&As[r*16 + kq] = *(const float4*)&A[(size_t)(row0 + r)*Hq + kt + kq];
            int kk = tid >> 4, cq = (tid & 15) << 2;
            *(float4*)&Ws[kk*64 + cq] = *(const float4*)&W[(size_t)(kt + kk)*Hq + col0 + cq];
        }
        __syncthreads();
        #pragma unroll
        for (int k = 0; k < 16; k++) {
            float4 wv = *(const float4*)&Ws[k*64 + tx*4];
            float a0 = As[(ty*4+0)*16 + k];
            float a1 = As[(ty*4+1)*16 + k];
            float a2 = As[(ty*4+2)*16 + k];
            float a3 = As[(ty*4+3)*16 + k];
            acc[0][0] = fmaf(a0, wv.x, acc[0][0]); acc[0][1] = fmaf(a0, wv.y, acc[0][1]);
            acc[0][2] = fmaf(a0, wv.z, acc[0][2]); acc[0][3] = fmaf(a0, wv.w, acc[0][3]);
            acc[1][0] = fmaf(a1, wv.x, acc[1][0]); acc[1][1] = fmaf(a1, wv.y, acc[1][1]);
            acc[1][2] = fmaf(a1, wv.z, acc[1][2]); acc[1][3] = fmaf(a1, wv.w, acc[1][3]);
            acc[2][0] = fmaf(a2, wv.x, acc[2][0]); acc[2][1] = fmaf(a2, wv.y, acc[2][1]);
            acc[2][2] = fmaf(a2, wv.z, acc[2][2]); acc[2][3] = fmaf(a2, wv.w, acc[2][3]);
            acc[3][0] = fmaf(a3, wv.x, acc[3][0]); acc[3][1] = fmaf(a3, wv.y, acc[3][1]);
            acc[3][2] = fmaf(a3, wv.z, acc[3][2]); acc[3][3] = fmaf(a3, wv.w, acc[3][3]);
        }
        __syncthreads();
    }

    float4 bv = *(const float4*)&bias[col0 + tx*4];
    #pragma unroll
    for (int i = 0; i < 4; i++) {
        float4 o;
        o.x = fmaxf(acc[i][0] + bv.x, 0.f);
        o.y = fmaxf(acc[i][1] + bv.y, 0.f);
        o.z = fmaxf(acc[i][2] + bv.z, 0.f);
        o.w = fmaxf(acc[i][3] + bv.w, 0.f);
        *(float4*)&g_hidden[(size_t)(row0 + ty*4 + i)*Hq + col0 + tx*4] = o;
    }
}

// ---------------- fc2: out = sigmoid(hidden @ fc2_w + b2) ----------------
__global__ void fc2_kernel(const float* __restrict__ w2,   // [512, 16]
                           const float* __restrict__ b2,
                           float* __restrict__ out) {
    __shared__ float w2s[Hq*Aq];   // 32 KB
    const int tid = threadIdx.x;   // 256
    for (int e = tid; e < Hq*Aq; e += 256) w2s[e] = w2[e];
    __syncthreads();

    const int r = tid >> 4;        // 16 rows per block
    const int a = tid & 15;
    const size_t row = (size_t)blockIdx.x * 16 + r;
    const float* hrow = &g_hidden[row*Hq];

    float acc = 0.f;
    #pragma unroll 8
    for (int k = 0; k < Hq; k += 4) {
        float4 hv = *(const float4*)&hrow[k];
        acc = fmaf(hv.x, w2s[(k+0)*Aq + a], acc);
        acc = fmaf(hv.y, w2s[(k+1)*Aq + a], acc);
        acc = fmaf(hv.z, w2s[(k+2)*Aq + a], acc);
        acc = fmaf(hv.w, w2s[(k+3)*Aq + a], acc);
    }
    float v = acc + b2[a];
    out[row*Aq + a] = 1.f / (1.f + __expf(-v));
}

extern "C" void kernel_launch(void* const* d_in, const int* in_sizes, int n_in,
                              void* d_out, int out_size) {
    const float* inp  = (const float*)d_in[0];
    const float* hn   = (const float*)d_in[1];
    const float* w_hh = (const float*)d_in[2];
    const float* w_ih = (const float*)d_in[3];
    const float* fc1w = (const float*)d_in[4];
    const float* fc1b = (const float*)d_in[5];
    const float* fc2w = (const float*)d_in[6];
    const float* fc2b = (const float*)d_in[7];
    float* out = (float*)d_out;

    xp_kernel<<<dim3(32, 32), 512>>>(inp, w_ih);
    rnn_kernel<<<GRNN, 256>>>(hn, w_hh, out);
    fc1_kernel<<<dim3(8, 512), 256>>>(out + RNN_OFF, fc1w, fc1b);
    fc2_kernel<<<(Bq*Tq)/16, 256>>>(fc2w, fc2b, out);
}

// round 2
// speedup vs baseline: 1.0315x; 1.0315x over previous
#include <cuda_runtime.h>
#include <cuda_fp16.h>

#define Bq 32
#define Tq 1024
#define Iq 64
#define Hq 512
#define Aq 16

#define OUT_N  (Bq*Tq*Aq)          // 524288
#define HN_N   (Bq*Hq)             // 16384
#define HN_OFF OUT_N
#define RNN_OFF (OUT_N + HN_N)     // 540672

#define GRNN 128                   // persistent RNN blocks (must be <= resident CTAs)
#define JPB  4                     // Hq / GRNN columns per block
#define HP   520                   // padded fp16 h row (bank-conflict-free, 16B-aligned rows)
#define WP   516                   // padded fp32 W row

// ---- scratch (static device globals: allocation-free) ----
__device__ float  g_xp[Tq*Bq*Hq];       // x_proj [t][b][j]   (64 MB)
__device__ float  g_hidden[Bq*Tq*Hq];   // fc1 output [row][k] (64 MB)
__device__ __align__(16) __half g_h16[2][Bq*Hq]; // h state transport, double-buffered
__device__ unsigned g_count;
__device__ unsigned g_gen;

// ---------------- grid-wide barrier (generation counter, replay-safe) ----------------
__device__ __forceinline__ void grid_barrier(int nb) {
    __syncthreads();
    if (threadIdx.x == 0) {
        __threadfence();
        volatile unsigned* genp = &g_gen;
        unsigned my = *genp;
        unsigned old = atomicAdd(&g_count, 1u);
        if (old == (unsigned)(nb - 1)) {
            atomicExch(&g_count, 0u);
            __threadfence();
            atomicAdd(&g_gen, 1u);
        } else {
            while (*genp == my) { }
        }
        __threadfence();
    }
    __syncthreads();
}

// ---------------- x_proj: xp[t][b][j] = sum_i inp[b][t][i] * w_ih[i][j] ----------------
__global__ void xp_kernel(const float* __restrict__ inp, const float* __restrict__ w_ih) {
    const int b   = blockIdx.x;   // 32
    const int tc  = blockIdx.y;   // 32 chunks of 32 timesteps
    const int tid = threadIdx.x;  // 512 (j)
    __shared__ float s_in[32*64];
    const float* src = inp + (size_t)b*Tq*Iq + (size_t)tc*32*Iq; // contiguous 2048 floats
    ((float4*)s_in)[tid] = ((const float4*)src)[tid];
    __syncthreads();

    float acc[32];
    #pragma unroll
    for (int tt = 0; tt < 32; tt++) acc[tt] = 0.f;

    #pragma unroll 8
    for (int i = 0; i < Iq; i++) {
        float w = w_ih[i*Hq + tid];
        #pragma unroll
        for (int tt = 0; tt < 32; tt++)
            acc[tt] = fmaf(s_in[tt*64 + i], w, acc[tt]);
    }
    #pragma unroll
    for (int tt = 0; tt < 32; tt++)
        g_xp[(size_t)(tc*32 + tt)*(Bq*Hq) + b*Hq + tid] = acc[tt];
}

// ---------------- persistent RNN scan ----------------
// block owns 4 output columns of w_hh (weight-stationary in SMEM).
// thread (ks, b, jl): partial dot over half the k range; reduce pairs via SMEM.
__global__ void __launch_bounds__(256, 1)
rnn_kernel(const float* __restrict__ hn, const float* __restrict__ w_hh,
           float* __restrict__ outbuf) {
    __shared__ __align__(16) __half h_s[32*HP];
    __shared__ float W_s[JPB*WP];
    __shared__ float psum[256];

    const int tid = threadIdx.x;
    const int bid = blockIdx.x;
    const int j0  = bid * JPB;

    // stationary weight slice: W_s[jl][k] = w_hh[k][j0+jl]
    for (int e = tid; e < JPB*Hq; e += 256) {
        int jl = e >> 9;
        int k  = e & 511;
        W_s[jl*WP + k] = w_hh[k*Hq + j0 + jl];
    }
    // h_0 = hn -> fp16 transport buffer 0
    for (int e = bid*256 + tid; e < Bq*Hq; e += GRNN*256)
        g_h16[0][e] = __float2half(hn[e]);

    grid_barrier(GRNN);

    const int jl    = tid & 3;
    const int bb    = (tid >> 2) & 31;
    const int ks    = tid >> 7;       // 0/1: k-split
    const int kbase = ks << 8;        // 0 or 256

    for (int t = 0; t < Tq; t++) {
        // stage full h state (fp16, 32 KB) into padded SMEM, L1-bypassing loads
        const int4* src = (const int4*)g_h16[t & 1];
        for (int e = tid; e < 2048; e += 256) {
            int row = e >> 6;
            int col = e & 63;
            ((int4*)(&h_s[row*HP]))[col] = __ldcg(&src[row*64 + col]);
        }
        __syncthreads();

        const __half* hrow = &h_s[bb*HP + kbase];
        const float*  wrow = &W_s[jl*WP + kbase];
        float acc = 0.f;
        #pragma unroll
        for (int k = 0; k < 256; k += 4) {
            float4  wv  = *(const float4*)(wrow + k);
            __half2 h01 = *(const __half2*)(hrow + k);
            __half2 h23 = *(const __half2*)(hrow + k + 2);
            float2  f01 = __half22float2(h01);
            float2  f23 = __half22float2(h23);
            acc = fmaf(f01.x, wv.x, acc);
            acc = fmaf(f01.y, wv.y, acc);
            acc = fmaf(f23.x, wv.z, acc);
            acc = fmaf(f23.y, wv.w, acc);
        }
        psum[tid] = acc;
        __syncthreads();

        if (tid < 128) {
            int b2 = tid >> 2;
            int j2 = (tid & 3) + j0;
            float v = psum[tid] + psum[tid + 128]
                    + g_xp[(size_t)t*(Bq*Hq) + b2*Hq + j2];
            float hval = 1.f / (1.f + __expf(-v));
            outbuf[RNN_OFF + (size_t)b2*Tq*Hq + (size_t)t*Hq + j2] = hval;  // rnn_out (fp32 exact)
            g_h16[(t + 1) & 1][b2*Hq + j2] = __float2half(hval);           // transport
            if (t == Tq - 1)
                outbuf[HN_OFF + b2*Hq + j2] = hval;                        // hn_last
        }
        grid_barrier(GRNN);
    }
}

// ---------------- fc1: hidden = relu(rnn_out @ fc1_w + b1), 64x64 tiles ----------------
__global__ void fc1_kernel(const float* __restrict__ A,   // [32768, 512] = rnn_out
                           const float* __restrict__ W,   // [512, 512]
                           const float* __restrict__ bias) {
    __shared__ float As[64*16];
    __shared__ float Ws[16*64];
    const int tid = threadIdx.x;      // 256
    const int bx = blockIdx.x;        // 8 col tiles
    const int by = blockIdx.y;        // 512 row tiles
    const int tx = tid & 15, ty = tid >> 4;
    const int row0 = by*64, col0 = bx*64;

    float acc[4][4];
    #pragma unroll
    for (int i = 0; i < 4; i++)
        #pragma unroll
        for (int j = 0; j < 4; j++) acc[i][j] = 0.f;

    for (int kt = 0; kt < Hq; kt += 16) {
        {
            int r  = tid >> 2, kq = (tid & 3) << 2;
            *(float4*)&As[r*16 + kq] = *(const float4*)&A[(size_t)(row0 + r)*Hq + kt + kq];
            int kk = tid >> 4, cq = (tid & 15) << 2;
            *(float4*)&Ws[kk*64 + cq] = *(const float4*)&W[(size_t)(kt + kk)*Hq + col0 + cq];
        }
        __syncthreads();
        #pragma unroll
        for (int k = 0; k < 16; k++) {
            float4 wv = *(const float4*)&Ws[k*64 + tx*4];
            float a0 = As[(ty*4+0)*16 + k];
            float a1 = As[(ty*4+1)*16 + k];
            float a2 = As[(ty*4+2)*16 + k];
            float a3 = As[(ty*4+3)*16 + k];
            acc[0][0] = fmaf(a0, wv.x, acc[0][0]); acc[0][1] = fmaf(a0, wv.y, acc[0][1]);
            acc[0][2] = fmaf(a0, wv.z, acc[0][2]); acc[0][3] = fmaf(a0, wv.w, acc[0][3]);
            acc[1][0] = fmaf(a1, wv.x, acc[1][0]); acc[1][1] = fmaf(a1, wv.y, acc[1][1]);
            acc[1][2] = fmaf(a1, wv.z, acc[1][2]); acc[1][3] = fmaf(a1, wv.w, acc[1][3]);
            acc[2][0] = fmaf(a2, wv.x, acc[2][0]); acc[2][1] = fmaf(a2, wv.y, acc[2][1]);
            acc[2][2] = fmaf(a2, wv.z, acc[2][2]); acc[2][3] = fmaf(a2, wv.w, acc[2][3]);
            acc[3][0] = fmaf(a3, wv.x, acc[3][0]); acc[3][1] = fmaf(a3, wv.y, acc[3][1]);
            acc[3][2] = fmaf(a3, wv.z, acc[3][2]); acc[3][3] = fmaf(a3, wv.w, acc[3][3]);
        }
        __syncthreads();
    }

    float4 bv = *(const float4*)&bias[col0 + tx*4];
    #pragma unroll
    for (int i = 0; i < 4; i++) {
        float4 o;
        o.x = fmaxf(acc[i][0] + bv.x, 0.f);
        o.y = fmaxf(acc[i][1] + bv.y, 0.f);
        o.z = fmaxf(acc[i][2] + bv.z, 0.f);
        o.w = fmaxf(acc[i][3] + bv.w, 0.f);
        *(float4*)&g_hidden[(size_t)(row0 + ty*4 + i)*Hq + col0 + tx*4] = o;
    }
}

// ---------------- fc2: out = sigmoid(hidden @ fc2_w + b2) ----------------
__global__ void fc2_kernel(const float* __restrict__ w2,   // [512, 16]
                           const float* __restrict__ b2,
                           float* __restrict__ out) {
    __shared__ float w2s[Hq*Aq];   // 32 KB
    const int tid = threadIdx.x;   // 256
    for (int e = tid; e < Hq*Aq; e += 256) w2s[e] = w2[e];
    __syncthreads();

    const int r = tid >> 4;        // 16 rows per block
    const int a = tid & 15;
    const size_t row = (size_t)blockIdx.x * 16 + r;
    const float* hrow = &g_hidden[row*Hq];

    float acc = 0.f;
    #pragma unroll 8
    for (int k = 0; k < Hq; k += 4) {
        float4 hv = *(const float4*)&hrow[k];
        acc = fmaf(hv.x, w2s[(k+0)*Aq + a], acc);
        acc = fmaf(hv.y, w2s[(k+1)*Aq + a], acc);
        acc = fmaf(hv.z, w2s[(k+2)*Aq + a], acc);
        acc = fmaf(hv.w, w2s[(k+3)*Aq + a], acc);
    }
    float v = acc + b2[a];
    out[row*Aq + a] = 1.f / (1.f + __expf(-v));
}

extern "C" void kernel_launch(void* const* d_in, const int* in_sizes, int n_in,
                              void* d_out, int out_size) {
    const float* inp  = (const float*)d_in[0];
    const float* hn   = (const float*)d_in[1];
    const float* w_hh = (const float*)d_in[2];
    const float* w_ih = (const float*)d_in[3];
    const float* fc1w = (const float*)d_in[4];
    const float* fc1b = (const float*)d_in[5];
    const float* fc2w = (const float*)d_in[6];
    const float* fc2b = (const float*)d_in[7];
    float* out = (float*)d_out;

    xp_kernel<<<dim3(32, 32), 512>>>(inp, w_ih);
    rnn_kernel<<<GRNN, 256>>>(hn, w_hh, out);
    fc1_kernel<<<dim3(8, 512), 256>>>(out + RNN_OFF, fc1w, fc1b);
    fc2_kernel<<<(Bq*Tq)/16, 256>>>(fc2w, fc2b, out);
}

// round 3
// speedup vs baseline: 1.9836x; 1.9231x over previous
#include <cuda_runtime.h>
#include <cstdint>

#define Bq 32
#define Tq 1024
#define Iq 64
#define Hq 512
#define Aq 16

#define OUT_N  (Bq*Tq*Aq)          // 524288
#define HN_N   (Bq*Hq)             // 16384
#define HN_OFF OUT_N
#define RNN_OFF (OUT_N + HN_N)     // 540672

#define CLU 8                      // CTAs per cluster (portable max)
#define NCL 16                     // clusters (16*8 = 128 CTAs)
#define NB  2                      // batches per cluster
#define TXB 4096                   // bytes received per mbarrier phase: 8 CTAs * 128 vals * 4B

// ---- scratch (static device globals: allocation-free) ----
__device__ float g_xp[Tq*Bq*Hq];       // x_proj [t][b][j]   (64 MB)
__device__ float g_hidden[(size_t)Bq*Tq*Hq];   // fc1 output (64 MB)

// ================= helpers =================
__device__ __forceinline__ uint32_t smem_u32(const void* p) {
    uint32_t a;
    asm("{ .reg .u64 t; cvta.to.shared.u64 t, %1; cvt.u32.u64 %0, t; }" : "=r"(a) : "l"(p));
    return a;
}
__device__ __forceinline__ uint32_t mapa_u32(uint32_t laddr, uint32_t rank) {
    uint32_t r;
    asm("mapa.shared::cluster.u32 %0, %1, %2;" : "=r"(r) : "r"(laddr), "r"(rank));
    return r;
}
__device__ __forceinline__ void st_async_f32(uint32_t raddr, float v, uint32_t rmbar) {
    asm volatile("st.async.shared::cluster.mbarrier::complete_tx::bytes.b32 [%0], %1, [%2];"
                 :: "r"(raddr), "f"(v), "r"(rmbar) : "memory");
}
__device__ __forceinline__ void mbar_init(uint32_t mbar, uint32_t cnt) {
    asm volatile("mbarrier.init.shared.b64 [%0], %1;" :: "r"(mbar), "r"(cnt) : "memory");
}
__device__ __forceinline__ void mbar_arrive_expect_tx(uint32_t mbar, uint32_t tx) {
    asm volatile("mbarrier.arrive.expect_tx.shared.b64 _, [%0], %1;" :: "r"(mbar), "r"(tx) : "memory");
}
__device__ __forceinline__ void mbar_wait_parity(uint32_t mbar, uint32_t parity) {
    asm volatile(
        "{\n\t"
        ".reg .pred P1;\n\t"
        "WAIT_LOOP_%=:\n\t"
        "mbarrier.try_wait.parity.acquire.cta.shared::cta.b64 P1, [%0], %1, 0x989680;\n\t"
        "@P1 bra.uni WAIT_DONE_%=;\n\t"
        "bra.uni WAIT_LOOP_%=;\n\t"
        "WAIT_DONE_%=:\n\t"
        "}" :: "r"(mbar), "r"(parity) : "memory");
}
__device__ __forceinline__ float2 ffma2(float2 a, float2 b, float2 c) {
    float2 d;
    asm("{\n\t"
        ".reg .b64 ra, rb, rc, rd;\n\t"
        "mov.b64 ra, {%2,%3};\n\t"
        "mov.b64 rb, {%4,%5};\n\t"
        "mov.b64 rc, {%6,%7};\n\t"
        "fma.rn.f32x2 rd, ra, rb, rc;\n\t"
        "mov.b64 {%0,%1}, rd;\n\t"
        "}"
        : "=f"(d.x), "=f"(d.y)
        : "f"(a.x), "f"(a.y), "f"(b.x), "f"(b.y), "f"(c.x), "f"(c.y));
    return d;
}

// ---------------- x_proj: xp[t][b][j] = sum_i inp[b][t][i] * w_ih[i][j] ----------------
__global__ void xp_kernel(const float* __restrict__ inp, const float* __restrict__ w_ih) {
    const int b   = blockIdx.x;   // 32
    const int tc  = blockIdx.y;   // 32 chunks of 32 timesteps
    const int tid = threadIdx.x;  // 512 (j)
    __shared__ float s_in[32*64];
    const float* src = inp + (size_t)b*Tq*Iq + (size_t)tc*32*Iq;
    ((float4*)s_in)[tid] = ((const float4*)src)[tid];
    __syncthreads();

    float acc[32];
    #pragma unroll
    for (int tt = 0; tt < 32; tt++) acc[tt] = 0.f;

    #pragma unroll 8
    for (int i = 0; i < Iq; i++) {
        float w = w_ih[i*Hq + tid];
        #pragma unroll
        for (int tt = 0; tt < 32; tt++)
            acc[tt] = fmaf(s_in[tt*64 + i], w, acc[tt]);
    }
    #pragma unroll
    for (int tt = 0; tt < 32; tt++)
        g_xp[(size_t)(tc*32 + tt)*(Bq*Hq) + b*Hq + tid] = acc[tt];
}

// ---------------- RNN scan: 16 independent clusters of 8 CTAs ----------------
// Cluster c handles batches {2c, 2c+1} for all T steps. CTA rank r owns output
// columns [r*64, r*64+64). Weights live in registers (128 regs/thread). h state
// is exchanged inside the cluster via st.async + mbarrier (double buffered).
__global__ void __launch_bounds__(256, 1) __cluster_dims__(CLU, 1, 1)
rnn_kernel(const float* __restrict__ hn, const float* __restrict__ w_hh,
           float* __restrict__ outbuf) {
    __shared__ __align__(16) float  h_s[2][NB*Hq];     // [buf][b*512 + k]  8KB
    __shared__ __align__(16) float2 psum[NB][512];     // [b][s*64 + col]   8KB
    __shared__ __align__(8)  unsigned long long mbar_s[2];

    const int tid = threadIdx.x;
    uint32_t rank;
    asm("mov.u32 %0, %%cluster_ctarank;" : "=r"(rank));
    const int cid = blockIdx.x >> 3;        // cluster id 0..15
    const int j0  = (int)rank * 64;         // column slice base
    const int s   = tid >> 5;               // k-segment 0..7 (one warp each)
    const int jl  = tid & 31;               // column pair index 0..31
    const int kb  = s * 64;

    // ---- load stationary W slice into registers (k-pair packed) ----
    // Wc0[m] = (w_hh[kb+2m][j0+2jl], w_hh[kb+2m+1][j0+2jl]); Wc1 same for col+1
    float2 Wc0[32], Wc1[32];
    {
        const float* wbase = w_hh + (size_t)kb*Hq + j0 + jl*2;
        #pragma unroll
        for (int m = 0; m < 32; m++) {
            const float* wp = wbase + (size_t)(2*m)*Hq;
            Wc0[m] = make_float2(wp[0], wp[Hq]);
            Wc1[m] = make_float2(wp[1], wp[Hq + 1]);
        }
    }
    // ---- h0 into buffer 0 ----
    for (int e = tid; e < NB*Hq; e += 256) {
        int b = e >> 9, k = e & 511;
        h_s[0][e] = hn[(size_t)(cid*NB + b)*Hq + k];
    }
    const uint32_t mbar0 = smem_u32(&mbar_s[0]);
    if (tid == 0) { mbar_init(mbar0, 1); mbar_init(mbar0 + 8, 1); }
    __syncthreads();
    // all peers' mbarriers + h buffers ready before any remote traffic
    asm volatile("barrier.cluster.arrive.aligned;" ::: "memory");
    asm volatile("barrier.cluster.wait.aligned;"   ::: "memory");

    const int fb = tid >> 6;                 // finisher batch (tid<128)
    const int fc = tid & 63;                 // finisher column (local)
    const uint32_t h_push_base = smem_u32(&h_s[0][0]);

    for (int t = 0; t < Tq; t++) {
        const int cur = t & 1, nxt = cur ^ 1;
        if (t > 0) mbar_wait_parity(mbar0 + 8u*cur, (uint32_t)(((t - 1) >> 1) & 1));
        if (tid == 0 && t < Tq - 1) mbar_arrive_expect_tx(mbar0 + 8u*nxt, TXB);

        // prefetch xp for the finisher phase (in flight during compute)
        float xpv = 0.f;
        if (tid < 128)
            xpv = __ldcg(&g_xp[(size_t)t*(Bq*Hq) + (cid*NB + fb)*Hq + j0 + fc]);

        // ---- main GEMV: 2 batches x 2 cols, k-pair packed f32x2 ----
        const float* hb0 = &h_s[cur][0];
        const float* hb1 = &h_s[cur][Hq];
        float2 a00 = {0.f,0.f}, a01 = {0.f,0.f}, a10 = {0.f,0.f}, a11 = {0.f,0.f};
        #pragma unroll
        for (int m = 0; m < 32; m++) {
            float2 h0 = *(const float2*)&hb0[kb + 2*m];   // broadcast LDS
            float2 h1 = *(const float2*)&hb1[kb + 2*m];
            a00 = ffma2(h0, Wc0[m], a00);
            a01 = ffma2(h0, Wc1[m], a01);
            a10 = ffma2(h1, Wc0[m], a10);
            a11 = ffma2(h1, Wc1[m], a11);
        }
        *(float4*)&psum[0][kb + jl*2] = make_float4(a00.x, a00.y, a01.x, a01.y);
        *(float4*)&psum[1][kb + jl*2] = make_float4(a10.x, a10.y, a11.x, a11.y);
        __syncthreads();

        // ---- finish: reduce 8 segments, sigmoid, store, push to peers ----
        if (tid < 128) {
            float2 acc = psum[fb][fc];
            #pragma unroll
            for (int s2 = 1; s2 < 8; s2++) {
                float2 p = psum[fb][s2*64 + fc];
                acc.x += p.x; acc.y += p.y;
            }
            float v  = acc.x + acc.y + xpv;
            float hv = 1.f / (1.f + __expf(-v));
            const size_t bglob = (size_t)(cid*NB + fb);
            outbuf[RNN_OFF + bglob*Tq*Hq + (size_t)t*Hq + j0 + fc] = hv;
            if (t == Tq - 1) {
                outbuf[HN_OFF + bglob*Hq + j0 + fc] = hv;
            } else {
                uint32_t loff = h_push_base + (uint32_t)((nxt*NB*Hq + fb*Hq + j0 + fc) * 4);
                uint32_t lmb  = mbar0 + 8u*nxt;
                #pragma unroll
                for (uint32_t r = 0; r < CLU; r++)
                    st_async_f32(mapa_u32(loff, r), hv, mapa_u32(lmb, r));
            }
        }
        __syncthreads();   // psum reuse + uniform re-entry
    }
}

// ---------------- fc1: hidden = relu(rnn_out @ fc1_w + b1), 64x64 tiles, f32x2 ----------------
__global__ void __launch_bounds__(256) fc1_kernel(const float* __restrict__ A,   // [32768, 512]
                                                  const float* __restrict__ W,   // [512, 512]
                                                  const float* __restrict__ bias) {
    __shared__ __align__(16) float  As[64*32];    // [r][k] 8KB
    __shared__ __align__(16) float2 Ws2[16*64];   // [kk][c] = (W[2kk][c], W[2kk+1][c]) 8KB
    const int tid = threadIdx.x;      // 256
    const int bx = blockIdx.x;        // 8 col tiles
    const int by = blockIdx.y;        // 512 row tiles
    const int tx = tid & 15, ty = tid >> 4;
    const int row0 = by*64, col0 = bx*64;

    float2 acc[4][4];
    #pragma unroll
    for (int i = 0; i < 4; i++)
        #pragma unroll
        for (int j = 0; j < 4; j++) acc[i][j] = make_float2(0.f, 0.f);

    for (int kt = 0; kt < Hq; kt += 32) {
        {
            int r = tid >> 3, kq = (tid & 7) << 2;
            *(float4*)&As[r*32 + kq]      = *(const float4*)&A[(size_t)(row0 + r)*Hq + kt + kq];
            *(float4*)&As[(r+32)*32 + kq] = *(const float4*)&A[(size_t)(row0 + r + 32)*Hq + kt + kq];
            #pragma unroll
            for (int i = 0; i < 4; i++) {
                int u = tid + i*256;
                int kk = u >> 6, c = u & 63;
                const float* wp = &W[(size_t)(kt + 2*kk)*Hq + col0 + c];
                Ws2[kk*64 + c] = make_float2(wp[0], wp[Hq]);
            }
        }
        __syncthreads();
        #pragma unroll
        for (int kk = 0; kk < 16; kk++) {
            float4 wA = *(const float4*)&Ws2[kk*64 + tx*4];
            float4 wB = *(const float4*)&Ws2[kk*64 + tx*4 + 2];
            float2 w0 = make_float2(wA.x, wA.y), w1 = make_float2(wA.z, wA.w);
            float2 w2 = make_float2(wB.x, wB.y), w3 = make_float2(wB.z, wB.w);
            #pragma unroll
            for (int r4 = 0; r4 < 4; r4++) {
                float2 a2 = *(const float2*)&As[(ty*4 + r4)*32 + 2*kk];
                acc[r4][0] = ffma2(a2, w0, acc[r4][0]);
                acc[r4][1] = ffma2(a2, w1, acc[r4][1]);
                acc[r4][2] = ffma2(a2, w2, acc[r4][2]);
                acc[r4][3] = ffma2(a2, w3, acc[r4][3]);
            }
        }
        __syncthreads();
    }

    float4 bv = *(const float4*)&bias[col0 + tx*4];
    #pragma unroll
    for (int i = 0; i < 4; i++) {
        float4 o;
        o.x = fmaxf(acc[i][0].x + acc[i][0].y + bv.x, 0.f);
        o.y = fmaxf(acc[i][1].x + acc[i][1].y + bv.y, 0.f);
        o.z = fmaxf(acc[i][2].x + acc[i][2].y + bv.z, 0.f);
        o.w = fmaxf(acc[i][3].x + acc[i][3].y + bv.w, 0.f);
        *(float4*)&g_hidden[(size_t)(row0 + ty*4 + i)*Hq + col0 + tx*4] = o;
    }
}

// ---------------- fc2: out = sigmoid(hidden @ fc2_w + b2) ----------------
__global__ void fc2_kernel(const float* __restrict__ w2,   // [512, 16]
                           const float* __restrict__ b2,
                           float* __restrict__ out) {
    __shared__ float w2s[Hq*Aq];   // 32 KB
    const int tid = threadIdx.x;   // 256
    for (int e = tid; e < Hq*Aq; e += 256) w2s[e] = w2[e];
    __syncthreads();

    const int r = tid >> 4;        // 16 rows per block
    const int a = tid & 15;
    const size_t row = (size_t)blockIdx.x * 16 + r;
    const float* hrow = &g_hidden[row*Hq];

    float acc = 0.f;
    #pragma unroll 8
    for (int k = 0; k < Hq; k += 4) {
        float4 hv = *(const float4*)&hrow[k];
        acc = fmaf(hv.x, w2s[(k+0)*Aq + a], acc);
        acc = fmaf(hv.y, w2s[(k+1)*Aq + a], acc);
        acc = fmaf(hv.z, w2s[(k+2)*Aq + a], acc);
        acc = fmaf(hv.w, w2s[(k+3)*Aq + a], acc);
    }
    float v = acc + b2[a];
    out[row*Aq + a] = 1.f / (1.f + __expf(-v));
}

extern "C" void kernel_launch(void* const* d_in, const int* in_sizes, int n_in,
                              void* d_out, int out_size) {
    const float* inp  = (const float*)d_in[0];
    const float* hn   = (const float*)d_in[1];
    const float* w_hh = (const float*)d_in[2];
    const float* w_ih = (const float*)d_in[3];
    const float* fc1w = (const float*)d_in[4];
    const float* fc1b = (const float*)d_in[5];
    const float* fc2w = (const float*)d_in[6];
    const float* fc2b = (const float*)d_in[7];
    float* out = (float*)d_out;

    xp_kernel<<<dim3(32, 32), 512>>>(inp, w_ih);
    rnn_kernel<<<NCL*CLU, 256>>>(hn, w_hh, out);
    fc1_kernel<<<dim3(8, 512), 256>>>(out + RNN_OFF, fc1w, fc1b);
    fc2_kernel<<<(Bq*Tq)/16, 256>>>(fc2w, fc2b, out);
}